// round 8
// baseline (speedup 1.0000x reference)
#include <cuda_runtime.h>
#include <cstdint>

// Problem constants
#define NGRAPH 128
#define NODES  256
#define CH     64
#define ADJ_ELEMS   ((size_t)NGRAPH * NODES * NODES)   // 8388608
#define F_ELEMS     ((size_t)NGRAPH * NODES * CH)      // 2097152
#define F_BASE      (3 * ADJ_ELEMS)                    // 25165824
#define STR  72     // sF/sW row stride (floats); LDS.64 conflict-free (see R7)
#define SSTR 260    // staging row stride (floats); 1040 B, 16B-multiple

__device__ __forceinline__ int posk(int k) {
    return (k & ~7) + ((k & 3) << 1) + ((k >> 2) & 1);
}

__device__ __forceinline__ float tf32r(float x) {
    uint32_t u;
    asm("cvt.rna.tf32.f32 %0, %1;" : "=r"(u) : "f"(x));
    return __uint_as_float(u);
}

__device__ __forceinline__ void mma_tf32(float d[4], const uint32_t a[4], const uint32_t b[2]) {
    asm volatile(
        "mma.sync.aligned.m16n8k8.row.col.f32.tf32.tf32.f32 "
        "{%0,%1,%2,%3},{%4,%5,%6,%7},{%8,%9},{%0,%1,%2,%3};\n"
        : "+f"(d[0]), "+f"(d[1]), "+f"(d[2]), "+f"(d[3])
        : "r"(a[0]), "r"(a[1]), "r"(a[2]), "r"(a[3]),
          "r"(b[0]), "r"(b[1]));
}

__device__ __forceinline__ float sigmoid_fast(float x) {
    return __fdividef(1.0f, 1.0f + __expf(-x));
}

__device__ __forceinline__ uint32_t smem_u32(const void* p) {
    uint32_t a;
    asm("{ .reg .u64 t; cvta.to.shared.u64 t, %1; cvt.u32.u64 %0, t; }" : "=r"(a) : "l"(p));
    return a;
}

__device__ __forceinline__ void bulk_store_s2g(void* gdst, uint32_t ssrc, uint32_t bytes) {
    asm volatile("cp.async.bulk.global.shared::cta.bulk_group [%0], [%1], %2;"
                 :: "l"(gdst), "r"(ssrc), "r"(bytes) : "memory");
}

// ---------------------------------------------------------------------------
// Fused kernel, 512 threads (16 warps), 1 CTA/SM, grid (128,3) = 384 CTAs.
// R7 compute structure; adjacency epilogue rerouted: sigmoid -> STS into
// padded smem staging -> per-row cp.async.bulk (TMA engine) -> gmem.
// Removes 2048 STG.64/CTA from the LSU (the largest measured pipe term).
// smem (floats): sF [256*72] | region [128*260] (sW overlays start; staging
// after MLP) | bias [128]  = 207,360 B total.
// ---------------------------------------------------------------------------
__global__ void __launch_bounds__(512, 1) fused_kernel(
    const float* __restrict__ z,
    const float* __restrict__ Wa1, const float* __restrict__ ba1,
    const float* __restrict__ Wa2, const float* __restrict__ ba2,
    const float* __restrict__ Wb1, const float* __restrict__ bb1,
    const float* __restrict__ Wb2, const float* __restrict__ bb2,
    const float* __restrict__ Wt1, const float* __restrict__ bt1,
    const float* __restrict__ Wt2, const float* __restrict__ bt2,
    float* __restrict__ out)
{
    extern __shared__ __align__(16) float smem[];
    float* sF    = smem;                        // [256][STR], k-permuted
    float* sRegion = smem + 256 * STR;          // sW (MLP phase) / staging (adj phase)
    float* sW    = sRegion;                     // [2][64][STR]
    float* sStag = sRegion;                     // [128][SSTR]
    float* sBias = smem + 256 * STR + 128 * SSTR;  // [128]

    const int g    = blockIdx.x;
    const int type = blockIdx.y;

    const float *W1, *B1, *W2, *B2;
    if (type == 0)      { W1 = Wa1; B1 = ba1; W2 = Wa2; B2 = ba2; }
    else if (type == 1) { W1 = Wb1; B1 = bb1; W2 = Wb2; B2 = bb2; }
    else                { W1 = Wt1; B1 = bt1; W2 = Wt2; B2 = bt2; }

    const int tid = threadIdx.x;
    const int warp = tid >> 5, lane = tid & 31;
    const int g8 = lane >> 2, q = lane & 3;

    // ---------------- Phase 0: loads ----------------
    const float* zG = z + (size_t)g * NODES * CH;
    for (int i = tid; i < NODES * CH / 4; i += 512) {
        int r = i >> 4, c4 = (i & 15) * 4;
        float4 v = *(const float4*)&zG[r * CH + c4];
        float* row = &sF[r * STR];
        row[posk(c4 + 0)] = v.x;
        row[posk(c4 + 1)] = v.y;
        row[posk(c4 + 2)] = v.z;
        row[posk(c4 + 3)] = v.w;
    }
#pragma unroll 1
    for (int l = 0; l < 2; ++l) {
        const float* W = l ? W2 : W1;
        float* w = sW + l * 64 * STR;
        for (int i = tid; i < 64 * 64; i += 512) {
            int k = i >> 6, n = i & 63;
            w[n * STR + posk(k)] = tf32r(W[i]);
        }
    }
    if (tid < 64)       sBias[tid] = B1[tid];
    else if (tid < 128) sBias[tid] = B2[tid - 64];
    __syncthreads();

    // ---------------- Phase 1: MLP (warp-private 16 rows, no block syncs) ----
    const int row0 = warp * 16;
    const int kq2 = 2 * q;
    float* __restrict__ fout = out + F_BASE + (size_t)type * F_ELEMS
                                   + (size_t)g * NODES * CH;

#pragma unroll 1
    for (int l = 0; l < 2; ++l) {
        const float* Wt   = sW + l * 64 * STR;
        const float* bias = sBias + l * 64;

        float acc[8][4];
#pragma unroll
        for (int nt = 0; nt < 8; ++nt)
#pragma unroll
            for (int e = 0; e < 4; ++e) acc[nt][e] = 0.0f;

#pragma unroll
        for (int k0 = 0; k0 < 8; ++k0) {
            const int kp = k0 * 8 + kq2;
            float2 la = *(const float2*)&sF[(row0 + g8)     * STR + kp];
            float2 lb = *(const float2*)&sF[(row0 + g8 + 8) * STR + kp];
            uint32_t af[4];
            af[0] = __float_as_uint(tf32r(la.x));
            af[1] = __float_as_uint(tf32r(lb.x));
            af[2] = __float_as_uint(tf32r(la.y));
            af[3] = __float_as_uint(tf32r(lb.y));
#pragma unroll
            for (int nt = 0; nt < 8; ++nt) {
                float2 wb = *(const float2*)&Wt[(nt * 8 + g8) * STR + kp];
                uint32_t bf[2] = {__float_as_uint(wb.x), __float_as_uint(wb.y)};
                mma_tf32(acc[nt], af, bf);
            }
        }
        __syncwarp();

#pragma unroll
        for (int nt = 0; nt < 8; ++nt) {
            const int c0 = nt * 8 + 2 * q;
            const int p0 = posk(c0), p1 = posk(c0 + 1);
            float v0 = fmaxf(acc[nt][0] + bias[c0],     0.0f);
            float v1 = fmaxf(acc[nt][1] + bias[c0 + 1], 0.0f);
            float v2 = fmaxf(acc[nt][2] + bias[c0],     0.0f);
            float v3 = fmaxf(acc[nt][3] + bias[c0 + 1], 0.0f);
            float* rA = &sF[(row0 + g8) * STR];
            float* rB = &sF[(row0 + g8 + 8) * STR];
            if (l == 0) {
                rA[p0] = v0; rA[p1] = v1;
                rB[p0] = v2; rB[p1] = v3;
            } else {
                *(float2*)&fout[(size_t)(row0 + g8)     * CH + c0] = make_float2(v0, v1);
                *(float2*)&fout[(size_t)(row0 + g8 + 8) * CH + c0] = make_float2(v2, v3);
                rA[p0] = tf32r(v0); rA[p1] = tf32r(v1);
                rB[p0] = tf32r(v2); rB[p1] = tf32r(v3);
            }
        }
        __syncwarp();
    }
    __syncthreads();    // full F (tf32) visible; sW dead from here (staging reuse)

    // ---------------- Phase 3: adjacency with TMA-store epilogue ----------------
    const int wm2 = warp >> 3;
    const int wn  = (warp & 7) * 32;
    float* __restrict__ O = out + ((size_t)type * NGRAPH + g) * (NODES * NODES);

#pragma unroll 1
    for (int hm = 0; hm < 2; ++hm) {
        const int rbase = hm * 128 + wm2 * 64;

        float acc[4][4][4];
#pragma unroll
        for (int mt = 0; mt < 4; ++mt)
#pragma unroll
            for (int nt = 0; nt < 4; ++nt)
#pragma unroll
                for (int e = 0; e < 4; ++e) acc[mt][nt][e] = 0.0f;

#pragma unroll
        for (int k0 = 0; k0 < 8; ++k0) {
            const int kp = k0 * 8 + kq2;
            uint32_t af[4][4], bf[4][2];
#pragma unroll
            for (int mt = 0; mt < 4; ++mt) {
                float2 la = *(const float2*)&sF[(rbase + mt * 16 + g8)     * STR + kp];
                float2 lb = *(const float2*)&sF[(rbase + mt * 16 + g8 + 8) * STR + kp];
                af[mt][0] = __float_as_uint(la.x);
                af[mt][1] = __float_as_uint(lb.x);
                af[mt][2] = __float_as_uint(la.y);
                af[mt][3] = __float_as_uint(lb.y);
            }
#pragma unroll
            for (int nt = 0; nt < 4; ++nt) {
                float2 vb = *(const float2*)&sF[(wn + nt * 8 + g8) * STR + kp];
                bf[nt][0] = __float_as_uint(vb.x);
                bf[nt][1] = __float_as_uint(vb.y);
            }
#pragma unroll
            for (int mt = 0; mt < 4; ++mt)
#pragma unroll
                for (int nt = 0; nt < 4; ++nt)
                    mma_tf32(acc[mt][nt], af[mt], bf[nt]);
        }

        // Staging reuse gate: half1 must not overwrite staging until half0's
        // bulk copies have completed. Issuing threads wait, then barrier.
        if (hm == 1) {
            if (tid < 128) asm volatile("cp.async.bulk.wait_group 0;" ::: "memory");
        }
        __syncthreads();

        // sigmoid -> STS into staging [128][SSTR] (local rows of this half)
#pragma unroll
        for (int mt = 0; mt < 4; ++mt) {
            const int rl = wm2 * 64 + mt * 16 + g8;   // 0..127 within half
#pragma unroll
            for (int nt = 0; nt < 4; ++nt) {
                const int col = wn + nt * 8 + 2 * q;
                float2 v0, v1;
                v0.x = sigmoid_fast(acc[mt][nt][0]);
                v0.y = sigmoid_fast(acc[mt][nt][1]);
                v1.x = sigmoid_fast(acc[mt][nt][2]);
                v1.y = sigmoid_fast(acc[mt][nt][3]);
                *(float2*)&sStag[rl * SSTR + col]       = v0;
                *(float2*)&sStag[(rl + 8) * SSTR + col] = v1;
            }
        }
        __syncthreads();   // staging fully written

        // Hand the 128 rows to the TMA engine (one 1KB bulk copy per row).
        if (tid < 128) {
            asm volatile("fence.proxy.async.shared::cta;" ::: "memory");
            uint32_t src = smem_u32(&sStag[tid * SSTR]);
            float* dst = O + (size_t)(hm * 128 + tid) * NODES;
            bulk_store_s2g(dst, src, NODES * (uint32_t)sizeof(float));
            asm volatile("cp.async.bulk.commit_group;" ::: "memory");
        }
    }

    // Drain outstanding bulk stores before exit.
    if (tid < 128) asm volatile("cp.async.bulk.wait_group 0;" ::: "memory");
}

extern "C" void kernel_launch(void* const* d_in, const int* in_sizes, int n_in,
                              void* d_out, int out_size) {
    const float* z   = (const float*)d_in[0];
    // d_in[1] = batch (int64): uniform segments, unused
    const float* Wa1 = (const float*)d_in[2];
    const float* ba1 = (const float*)d_in[3];
    const float* Wa2 = (const float*)d_in[4];
    const float* ba2 = (const float*)d_in[5];
    const float* Wb1 = (const float*)d_in[6];
    const float* bb1 = (const float*)d_in[7];
    const float* Wb2 = (const float*)d_in[8];
    const float* bb2 = (const float*)d_in[9];
    const float* Wt1 = (const float*)d_in[10];
    const float* bt1 = (const float*)d_in[11];
    const float* Wt2 = (const float*)d_in[12];
    const float* bt2 = (const float*)d_in[13];
    float* out = (float*)d_out;

    const int smem_bytes = (256 * STR + 128 * SSTR + 128) * (int)sizeof(float); // 207360
    cudaFuncSetAttribute(fused_kernel, cudaFuncAttributeMaxDynamicSharedMemorySize, smem_bytes);
    fused_kernel<<<dim3(NGRAPH, 3), 512, smem_bytes>>>(
        z, Wa1, ba1, Wa2, ba2, Wb1, bb1, Wb2, bb2, Wt1, bt1, Wt2, bt2, out);
}

// round 9
// speedup vs baseline: 1.1515x; 1.1515x over previous
#include <cuda_runtime.h>
#include <cstdint>

// Problem constants
#define NGRAPH 128
#define NODES  256
#define CH     64
#define ADJ_ELEMS   ((size_t)NGRAPH * NODES * NODES)   // 8388608
#define F_ELEMS     ((size_t)NGRAPH * NODES * CH)      // 2097152
#define F_BASE      (3 * ADJ_ELEMS)                    // 25165824
// smem row stride (floats). 72 -> 36 8B-words/row == 4 (mod 16), so LDS.64
// wavefront bank index = (4*g8 + q) mod 16: conflict-free.
#define STR 72

// k-dimension permutation: logical k -> physical slot, making (k, k+4)
// adjacent so fragment loads are single LDS.64.
__device__ __forceinline__ int posk(int k) {
    return (k & ~7) + ((k & 3) << 1) + ((k >> 2) & 1);
}

__device__ __forceinline__ float tf32r(float x) {
    uint32_t u;
    asm("cvt.rna.tf32.f32 %0, %1;" : "=r"(u) : "f"(x));
    return __uint_as_float(u);
}

__device__ __forceinline__ void mma_tf32(float d[4], const uint32_t a[4], const uint32_t b[2]) {
    asm volatile(
        "mma.sync.aligned.m16n8k8.row.col.f32.tf32.tf32.f32 "
        "{%0,%1,%2,%3},{%4,%5,%6,%7},{%8,%9},{%0,%1,%2,%3};\n"
        : "+f"(d[0]), "+f"(d[1]), "+f"(d[2]), "+f"(d[3])
        : "r"(a[0]), "r"(a[1]), "r"(a[2]), "r"(a[3]),
          "r"(b[0]), "r"(b[1]));
}

__device__ __forceinline__ float sigmoid_fast(float x) {
    return __fdividef(1.0f, 1.0f + __expf(-x));
}

// ---------------------------------------------------------------------------
// Fused kernel, 512 threads (16 warps), 1 CTA/SM, grid (128,3) = 384 CTAs.
// R7 structure (best: 67.6us) + anti-phase adjacency halves: even warps do
// half0's MMA while odd warps do half1's epilogue and vice versa, overlapping
// the tensor pipe with the MUFU/STG epilogue on every SMSP.
// Numerics bit-identical to R7.
// smem: sF [256][STR] + sW [2][64][STR] + bias[128] = 111104 B
// ---------------------------------------------------------------------------
__global__ void __launch_bounds__(512, 1) fused_kernel(
    const float* __restrict__ z,
    const float* __restrict__ Wa1, const float* __restrict__ ba1,
    const float* __restrict__ Wa2, const float* __restrict__ ba2,
    const float* __restrict__ Wb1, const float* __restrict__ bb1,
    const float* __restrict__ Wb2, const float* __restrict__ bb2,
    const float* __restrict__ Wt1, const float* __restrict__ bt1,
    const float* __restrict__ Wt2, const float* __restrict__ bt2,
    float* __restrict__ out)
{
    extern __shared__ __align__(16) float smem[];
    float* sF    = smem;                  // [256][STR], k-permuted
    float* sW    = smem + 256 * STR;      // [2][64][STR] tf32 weights, [n][posk(k)]
    float* sBias = sW + 2 * 64 * STR;     // [128]

    const int g    = blockIdx.x;
    const int type = blockIdx.y;

    const float *W1, *B1, *W2, *B2;
    if (type == 0)      { W1 = Wa1; B1 = ba1; W2 = Wa2; B2 = ba2; }
    else if (type == 1) { W1 = Wb1; B1 = bb1; W2 = Wb2; B2 = bb2; }
    else                { W1 = Wt1; B1 = bt1; W2 = Wt2; B2 = bt2; }

    const int tid = threadIdx.x;
    const int warp = tid >> 5, lane = tid & 31;
    const int g8 = lane >> 2, q = lane & 3;

    // ---------------- Phase 0: loads (scattered STS due to k-permutation) ---
    const float* zG = z + (size_t)g * NODES * CH;
    for (int i = tid; i < NODES * CH / 4; i += 512) {       // 4096 float4s
        int r = i >> 4, c4 = (i & 15) * 4;
        float4 v = *(const float4*)&zG[r * CH + c4];
        float* row = &sF[r * STR];
        row[posk(c4 + 0)] = v.x;
        row[posk(c4 + 1)] = v.y;
        row[posk(c4 + 2)] = v.z;
        row[posk(c4 + 3)] = v.w;
    }
#pragma unroll 1
    for (int l = 0; l < 2; ++l) {
        const float* W = l ? W2 : W1;
        float* w = sW + l * 64 * STR;
        for (int i = tid; i < 64 * 64; i += 512) {
            int k = i >> 6, n = i & 63;
            w[n * STR + posk(k)] = tf32r(W[i]);   // coalesced read, scattered store
        }
    }
    if (tid < 64)       sBias[tid] = B1[tid];
    else if (tid < 128) sBias[tid] = B2[tid - 64];
    __syncthreads();

    // ---------------- Phase 1: MLP (warp-private 16 rows, no block syncs) ----
    const int row0 = warp * 16;
    const int kq2 = 2 * q;   // physical offset of the (q, q+4) pair within a group
    float* __restrict__ fout = out + F_BASE + (size_t)type * F_ELEMS
                                   + (size_t)g * NODES * CH;

#pragma unroll 1
    for (int l = 0; l < 2; ++l) {
        const float* Wt   = sW + l * 64 * STR;
        const float* bias = sBias + l * 64;

        float acc[8][4];
#pragma unroll
        for (int nt = 0; nt < 8; ++nt)
#pragma unroll
            for (int e = 0; e < 4; ++e) acc[nt][e] = 0.0f;

#pragma unroll
        for (int k0 = 0; k0 < 8; ++k0) {
            const int kp = k0 * 8 + kq2;
            float2 la = *(const float2*)&sF[(row0 + g8)     * STR + kp];
            float2 lb = *(const float2*)&sF[(row0 + g8 + 8) * STR + kp];
            uint32_t af[4];
            af[0] = __float_as_uint(tf32r(la.x));   // A[g8][kc]
            af[1] = __float_as_uint(tf32r(lb.x));   // A[g8+8][kc]
            af[2] = __float_as_uint(tf32r(la.y));   // A[g8][kc+4]
            af[3] = __float_as_uint(tf32r(lb.y));   // A[g8+8][kc+4]
#pragma unroll
            for (int nt = 0; nt < 8; ++nt) {
                float2 wb = *(const float2*)&Wt[(nt * 8 + g8) * STR + kp];
                uint32_t bf[2] = {__float_as_uint(wb.x), __float_as_uint(wb.y)};
                mma_tf32(acc[nt], af, bf);
            }
        }
        __syncwarp();   // all lanes done reading this warp's sF rows

#pragma unroll
        for (int nt = 0; nt < 8; ++nt) {
            const int c0 = nt * 8 + 2 * q;
            const int p0 = posk(c0), p1 = posk(c0 + 1);
            float v0 = fmaxf(acc[nt][0] + bias[c0],     0.0f);
            float v1 = fmaxf(acc[nt][1] + bias[c0 + 1], 0.0f);
            float v2 = fmaxf(acc[nt][2] + bias[c0],     0.0f);
            float v3 = fmaxf(acc[nt][3] + bias[c0 + 1], 0.0f);
            float* rA = &sF[(row0 + g8) * STR];
            float* rB = &sF[(row0 + g8 + 8) * STR];
            if (l == 0) {
                rA[p0] = v0; rA[p1] = v1;
                rB[p0] = v2; rB[p1] = v3;
            } else {
                *(float2*)&fout[(size_t)(row0 + g8)     * CH + c0] = make_float2(v0, v1);
                *(float2*)&fout[(size_t)(row0 + g8 + 8) * CH + c0] = make_float2(v2, v3);
                rA[p0] = tf32r(v0); rA[p1] = tf32r(v1);
                rB[p0] = tf32r(v2); rB[p1] = tf32r(v3);
            }
        }
        __syncwarp();   // stores visible before next layer's lane-crossed reads
    }
    __syncthreads();    // full F (tf32, k-permuted) visible to all warps

    // ---------------- Phase 3: adjacency, anti-phase halves ----------------
    const int wm2 = warp >> 3;          // 0..1 -> 64-row block within half
    const int wn  = (warp & 7) * 32;    // 0..224
    const int hswap = warp & 1;         // odd warps take half1 first
    float* __restrict__ O = out + ((size_t)type * NGRAPH + g) * (NODES * NODES);

#pragma unroll 1
    for (int h = 0; h < 2; ++h) {
        const int hm = h ^ hswap;       // anti-phase: tensor of one half overlaps
        const int rbase = hm * 128 + wm2 * 64;   // epilogue of the other across warps

        float acc[4][4][4];
#pragma unroll
        for (int mt = 0; mt < 4; ++mt)
#pragma unroll
            for (int nt = 0; nt < 4; ++nt)
#pragma unroll
                for (int e = 0; e < 4; ++e) acc[mt][nt][e] = 0.0f;

#pragma unroll
        for (int k0 = 0; k0 < 8; ++k0) {
            const int kp = k0 * 8 + kq2;
            uint32_t af[4][4], bf[4][2];
#pragma unroll
            for (int mt = 0; mt < 4; ++mt) {
                float2 la = *(const float2*)&sF[(rbase + mt * 16 + g8)     * STR + kp];
                float2 lb = *(const float2*)&sF[(rbase + mt * 16 + g8 + 8) * STR + kp];
                af[mt][0] = __float_as_uint(la.x);
                af[mt][1] = __float_as_uint(lb.x);
                af[mt][2] = __float_as_uint(la.y);
                af[mt][3] = __float_as_uint(lb.y);
            }
#pragma unroll
            for (int nt = 0; nt < 4; ++nt) {
                float2 vb = *(const float2*)&sF[(wn + nt * 8 + g8) * STR + kp];
                bf[nt][0] = __float_as_uint(vb.x);
                bf[nt][1] = __float_as_uint(vb.y);
            }
#pragma unroll
            for (int mt = 0; mt < 4; ++mt)
#pragma unroll
                for (int nt = 0; nt < 4; ++nt)
                    mma_tf32(acc[mt][nt], af[mt], bf[nt]);
        }

#pragma unroll
        for (int mt = 0; mt < 4; ++mt) {
            const int row = rbase + mt * 16 + g8;
#pragma unroll
            for (int nt = 0; nt < 4; ++nt) {
                const int col = wn + nt * 8 + 2 * q;
                float2 v0, v1;
                v0.x = sigmoid_fast(acc[mt][nt][0]);
                v0.y = sigmoid_fast(acc[mt][nt][1]);
                v1.x = sigmoid_fast(acc[mt][nt][2]);
                v1.y = sigmoid_fast(acc[mt][nt][3]);
                *(float2*)&O[(size_t)row * NODES + col]       = v0;
                *(float2*)&O[(size_t)(row + 8) * NODES + col] = v1;
            }
        }
    }
}

extern "C" void kernel_launch(void* const* d_in, const int* in_sizes, int n_in,
                              void* d_out, int out_size) {
    const float* z   = (const float*)d_in[0];
    // d_in[1] = batch (int64): uniform segments, unused
    const float* Wa1 = (const float*)d_in[2];
    const float* ba1 = (const float*)d_in[3];
    const float* Wa2 = (const float*)d_in[4];
    const float* ba2 = (const float*)d_in[5];
    const float* Wb1 = (const float*)d_in[6];
    const float* bb1 = (const float*)d_in[7];
    const float* Wb2 = (const float*)d_in[8];
    const float* bb2 = (const float*)d_in[9];
    const float* Wt1 = (const float*)d_in[10];
    const float* bt1 = (const float*)d_in[11];
    const float* Wt2 = (const float*)d_in[12];
    const float* bt2 = (const float*)d_in[13];
    float* out = (float*)d_out;

    const int smem_bytes = (256 * STR + 2 * 64 * STR + 128) * (int)sizeof(float); // 111104
    cudaFuncSetAttribute(fused_kernel, cudaFuncAttributeMaxDynamicSharedMemorySize, smem_bytes);
    fused_kernel<<<dim3(NGRAPH, 3), 512, smem_bytes>>>(
        z, Wa1, ba1, Wa2, ba2, Wb1, bb1, Wb2, bb2, Wt1, bt1, Wt2, bt2, out);
}

// round 12
// speedup vs baseline: 1.1526x; 1.0009x over previous
#include <cuda_runtime.h>
#include <cstdint>

// Problem constants
#define NGRAPH 128
#define NODES  256
#define CH     64
#define ADJ_ELEMS   ((size_t)NGRAPH * NODES * NODES)   // 8388608
#define F_ELEMS     ((size_t)NGRAPH * NODES * CH)      // 2097152
#define F_BASE      (3 * ADJ_ELEMS)                    // 25165824
// smem row stride (floats). 72 -> 36 8B-words/row == 4 (mod 16), so LDS.64
// wavefront bank index = (4*g8 + q) mod 16: conflict-free.
#define STR 72

// k-dimension permutation: logical k -> physical slot, making (k, k+4)
// adjacent so fragment loads are single LDS.64.
__device__ __forceinline__ int posk(int k) {
    return (k & ~7) + ((k & 3) << 1) + ((k >> 2) & 1);
}

__device__ __forceinline__ float tf32r(float x) {
    uint32_t u;
    asm("cvt.rna.tf32.f32 %0, %1;" : "=r"(u) : "f"(x));
    return __uint_as_float(u);
}

__device__ __forceinline__ void mma_tf32(float d[4], const uint32_t a[4], const uint32_t b[2]) {
    asm volatile(
        "mma.sync.aligned.m16n8k8.row.col.f32.tf32.tf32.f32 "
        "{%0,%1,%2,%3},{%4,%5,%6,%7},{%8,%9},{%0,%1,%2,%3};\n"
        : "+f"(d[0]), "+f"(d[1]), "+f"(d[2]), "+f"(d[3])
        : "r"(a[0]), "r"(a[1]), "r"(a[2]), "r"(a[3]),
          "r"(b[0]), "r"(b[1]));
}

// sigmoid(x) = 0.5*tanh(x/2) + 0.5 — single MUFU op (tanh.approx) instead of
// the EX2+RCP pair. Halves the dominant MUFU term in the adjacency epilogue.
__device__ __forceinline__ float sigmoid_fast(float x) {
    float t;
    asm("tanh.approx.f32 %0, %1;" : "=f"(t) : "f"(x * 0.5f));
    return fmaf(t, 0.5f, 0.5f);
}

// ---------------------------------------------------------------------------
// Fused kernel, 512 threads (16 warps), 1 CTA/SM, grid (128,3) = 384 CTAs.
// R7 structure (best: 67.6us) with one-MUFU sigmoid in the adjacency epilogue.
// All other numerics / layout bit-identical to R7.
// smem: sF [256][STR] + sW [2][64][STR] + bias[128] = 111104 B
// ---------------------------------------------------------------------------
__global__ void __launch_bounds__(512, 1) fused_kernel(
    const float* __restrict__ z,
    const float* __restrict__ Wa1, const float* __restrict__ ba1,
    const float* __restrict__ Wa2, const float* __restrict__ ba2,
    const float* __restrict__ Wb1, const float* __restrict__ bb1,
    const float* __restrict__ Wb2, const float* __restrict__ bb2,
    const float* __restrict__ Wt1, const float* __restrict__ bt1,
    const float* __restrict__ Wt2, const float* __restrict__ bt2,
    float* __restrict__ out)
{
    extern __shared__ __align__(16) float smem[];
    float* sF    = smem;                  // [256][STR], k-permuted
    float* sW    = smem + 256 * STR;      // [2][64][STR] tf32 weights, [n][posk(k)]
    float* sBias = sW + 2 * 64 * STR;     // [128]

    const int g    = blockIdx.x;
    const int type = blockIdx.y;

    const float *W1, *B1, *W2, *B2;
    if (type == 0)      { W1 = Wa1; B1 = ba1; W2 = Wa2; B2 = ba2; }
    else if (type == 1) { W1 = Wb1; B1 = bb1; W2 = Wb2; B2 = bb2; }
    else                { W1 = Wt1; B1 = bt1; W2 = Wt2; B2 = bt2; }

    const int tid = threadIdx.x;
    const int warp = tid >> 5, lane = tid & 31;
    const int g8 = lane >> 2, q = lane & 3;

    // ---------------- Phase 0: loads (scattered STS due to k-permutation) ---
    const float* zG = z + (size_t)g * NODES * CH;
    for (int i = tid; i < NODES * CH / 4; i += 512) {       // 4096 float4s
        int r = i >> 4, c4 = (i & 15) * 4;
        float4 v = *(const float4*)&zG[r * CH + c4];
        float* row = &sF[r * STR];
        row[posk(c4 + 0)] = v.x;
        row[posk(c4 + 1)] = v.y;
        row[posk(c4 + 2)] = v.z;
        row[posk(c4 + 3)] = v.w;
    }
#pragma unroll 1
    for (int l = 0; l < 2; ++l) {
        const float* W = l ? W2 : W1;
        float* w = sW + l * 64 * STR;
        for (int i = tid; i < 64 * 64; i += 512) {
            int k = i >> 6, n = i & 63;
            w[n * STR + posk(k)] = tf32r(W[i]);   // coalesced read, scattered store
        }
    }
    if (tid < 64)       sBias[tid] = B1[tid];
    else if (tid < 128) sBias[tid] = B2[tid - 64];
    __syncthreads();

    // ---------------- Phase 1: MLP (warp-private 16 rows, no block syncs) ----
    const int row0 = warp * 16;
    const int kq2 = 2 * q;   // physical offset of the (q, q+4) pair within a group
    float* __restrict__ fout = out + F_BASE + (size_t)type * F_ELEMS
                                   + (size_t)g * NODES * CH;

#pragma unroll 1
    for (int l = 0; l < 2; ++l) {
        const float* Wt   = sW + l * 64 * STR;
        const float* bias = sBias + l * 64;

        float acc[8][4];
#pragma unroll
        for (int nt = 0; nt < 8; ++nt)
#pragma unroll
            for (int e = 0; e < 4; ++e) acc[nt][e] = 0.0f;

#pragma unroll
        for (int k0 = 0; k0 < 8; ++k0) {
            const int kp = k0 * 8 + kq2;
            float2 la = *(const float2*)&sF[(row0 + g8)     * STR + kp];
            float2 lb = *(const float2*)&sF[(row0 + g8 + 8) * STR + kp];
            uint32_t af[4];
            af[0] = __float_as_uint(tf32r(la.x));   // A[g8][kc]
            af[1] = __float_as_uint(tf32r(lb.x));   // A[g8+8][kc]
            af[2] = __float_as_uint(tf32r(la.y));   // A[g8][kc+4]
            af[3] = __float_as_uint(tf32r(lb.y));   // A[g8+8][kc+4]
#pragma unroll
            for (int nt = 0; nt < 8; ++nt) {
                float2 wb = *(const float2*)&Wt[(nt * 8 + g8) * STR + kp];
                uint32_t bf[2] = {__float_as_uint(wb.x), __float_as_uint(wb.y)};
                mma_tf32(acc[nt], af, bf);
            }
        }
        __syncwarp();   // all lanes done reading this warp's sF rows

#pragma unroll
        for (int nt = 0; nt < 8; ++nt) {
            const int c0 = nt * 8 + 2 * q;
            const int p0 = posk(c0), p1 = posk(c0 + 1);
            float v0 = fmaxf(acc[nt][0] + bias[c0],     0.0f);
            float v1 = fmaxf(acc[nt][1] + bias[c0 + 1], 0.0f);
            float v2 = fmaxf(acc[nt][2] + bias[c0],     0.0f);
            float v3 = fmaxf(acc[nt][3] + bias[c0 + 1], 0.0f);
            float* rA = &sF[(row0 + g8) * STR];
            float* rB = &sF[(row0 + g8 + 8) * STR];
            if (l == 0) {
                rA[p0] = v0; rA[p1] = v1;
                rB[p0] = v2; rB[p1] = v3;
            } else {
                *(float2*)&fout[(size_t)(row0 + g8)     * CH + c0] = make_float2(v0, v1);
                *(float2*)&fout[(size_t)(row0 + g8 + 8) * CH + c0] = make_float2(v2, v3);
                rA[p0] = tf32r(v0); rA[p1] = tf32r(v1);
                rB[p0] = tf32r(v2); rB[p1] = tf32r(v3);
            }
        }
        __syncwarp();   // stores visible before next layer's lane-crossed reads
    }
    __syncthreads();    // full F (tf32, k-permuted) visible to all warps

    // ---------------- Phase 3: adjacency ----------------
    const int wm2 = warp >> 3;          // 0..1 -> 64-row block within half
    const int wn  = (warp & 7) * 32;    // 0..224
    float* __restrict__ O = out + ((size_t)type * NGRAPH + g) * (NODES * NODES);

#pragma unroll 1
    for (int hm = 0; hm < 2; ++hm) {
        const int rbase = hm * 128 + wm2 * 64;

        float acc[4][4][4];
#pragma unroll
        for (int mt = 0; mt < 4; ++mt)
#pragma unroll
            for (int nt = 0; nt < 4; ++nt)
#pragma unroll
                for (int e = 0; e < 4; ++e) acc[mt][nt][e] = 0.0f;

#pragma unroll
        for (int k0 = 0; k0 < 8; ++k0) {
            const int kp = k0 * 8 + kq2;
            uint32_t af[4][4], bf[4][2];
#pragma unroll
            for (int mt = 0; mt < 4; ++mt) {
                float2 la = *(const float2*)&sF[(rbase + mt * 16 + g8)     * STR + kp];
                float2 lb = *(const float2*)&sF[(rbase + mt * 16 + g8 + 8) * STR + kp];
                af[mt][0] = __float_as_uint(la.x);
                af[mt][1] = __float_as_uint(lb.x);
                af[mt][2] = __float_as_uint(la.y);
                af[mt][3] = __float_as_uint(lb.y);
            }
#pragma unroll
            for (int nt = 0; nt < 4; ++nt) {
                float2 vb = *(const float2*)&sF[(wn + nt * 8 + g8) * STR + kp];
                bf[nt][0] = __float_as_uint(vb.x);
                bf[nt][1] = __float_as_uint(vb.y);
            }
#pragma unroll
            for (int mt = 0; mt < 4; ++mt)
#pragma unroll
                for (int nt = 0; nt < 4; ++nt)
                    mma_tf32(acc[mt][nt], af[mt], bf[nt]);
        }

#pragma unroll
        for (int mt = 0; mt < 4; ++mt) {
            const int row = rbase + mt * 16 + g8;
#pragma unroll
            for (int nt = 0; nt < 4; ++nt) {
                const int col = wn + nt * 8 + 2 * q;
                float2 v0, v1;
                v0.x = sigmoid_fast(acc[mt][nt][0]);
                v0.y = sigmoid_fast(acc[mt][nt][1]);
                v1.x = sigmoid_fast(acc[mt][nt][2]);
                v1.y = sigmoid_fast(acc[mt][nt][3]);
                *(float2*)&O[(size_t)row * NODES + col]       = v0;
                *(float2*)&O[(size_t)(row + 8) * NODES + col] = v1;
            }
        }
    }
}

extern "C" void kernel_launch(void* const* d_in, const int* in_sizes, int n_in,
                              void* d_out, int out_size) {
    const float* z   = (const float*)d_in[0];
    // d_in[1] = batch (int64): uniform segments, unused
    const float* Wa1 = (const float*)d_in[2];
    const float* ba1 = (const float*)d_in[3];
    const float* Wa2 = (const float*)d_in[4];
    const float* ba2 = (const float*)d_in[5];
    const float* Wb1 = (const float*)d_in[6];
    const float* bb1 = (const float*)d_in[7];
    const float* Wb2 = (const float*)d_in[8];
    const float* bb2 = (const float*)d_in[9];
    const float* Wt1 = (const float*)d_in[10];
    const float* bt1 = (const float*)d_in[11];
    const float* Wt2 = (const float*)d_in[12];
    const float* bt2 = (const float*)d_in[13];
    float* out = (float*)d_out;

    const int smem_bytes = (256 * STR + 2 * 64 * STR + 128) * (int)sizeof(float); // 111104
    cudaFuncSetAttribute(fused_kernel, cudaFuncAttributeMaxDynamicSharedMemorySize, smem_bytes);
    fused_kernel<<<dim3(NGRAPH, 3), 512, smem_bytes>>>(
        z, Wa1, ba1, Wa2, ba2, Wb1, bb1, Wb2, bb2, Wt1, bt1, Wt2, bt2, out);
}

// round 14
// speedup vs baseline: 1.3103x; 1.1369x over previous
#include <cuda_runtime.h>
#include <cstdint>

// Problem constants
#define NGRAPH 128
#define NODES  256
#define CH     64
#define ADJ_ELEMS   ((size_t)NGRAPH * NODES * NODES)   // 8388608
#define F_ELEMS     ((size_t)NGRAPH * NODES * CH)      // 2097152
#define F_BASE      (3 * ADJ_ELEMS)                    // 25165824
#define STR  72   // sZ/sW row stride (floats); LDS.64 conflict-free (see R7)
#define BSTR 40   // sB row stride (u32); 20 8B-words/row == 4 (mod 16): conflict-free

// k-dimension permutation (f32 buffers): (k, k+4) adjacent -> LDS.64.
__device__ __forceinline__ int posk(int k) {
    return (k & ~7) + ((k & 3) << 1) + ((k >> 2) & 1);
}

__device__ __forceinline__ float tf32r(float x) {
    uint32_t u;
    asm("cvt.rna.tf32.f32 %0, %1;" : "=r"(u) : "f"(x));
    return __uint_as_float(u);
}

__device__ __forceinline__ void mma_tf32(float d[4], const uint32_t a[4], const uint32_t b[2]) {
    asm volatile(
        "mma.sync.aligned.m16n8k8.row.col.f32.tf32.tf32.f32 "
        "{%0,%1,%2,%3},{%4,%5,%6,%7},{%8,%9},{%0,%1,%2,%3};\n"
        : "+f"(d[0]), "+f"(d[1]), "+f"(d[2]), "+f"(d[3])
        : "r"(a[0]), "r"(a[1]), "r"(a[2]), "r"(a[3]),
          "r"(b[0]), "r"(b[1]));
}

__device__ __forceinline__ void mma_bf16(float d[4], const uint32_t a[4], const uint32_t b[2]) {
    asm volatile(
        "mma.sync.aligned.m16n8k16.row.col.f32.bf16.bf16.f32 "
        "{%0,%1,%2,%3},{%4,%5,%6,%7},{%8,%9},{%0,%1,%2,%3};\n"
        : "+f"(d[0]), "+f"(d[1]), "+f"(d[2]), "+f"(d[3])
        : "r"(a[0]), "r"(a[1]), "r"(a[2]), "r"(a[3]),
          "r"(b[0]), "r"(b[1]));
}

// sigmoid(x) = 0.5*tanh(x/2)+0.5 — single MUFU (kept from R12, same rel_err).
__device__ __forceinline__ float sigmoid_fast(float x) {
    float t;
    asm("tanh.approx.f32 %0, %1;" : "=f"(t) : "f"(x * 0.5f));
    return fmaf(t, 0.5f, 0.5f);
}

// pack {lo,hi} f32 -> bf16x2 (lo in bits[15:0])
__device__ __forceinline__ uint32_t pack_bf16(float lo, float hi) {
    uint32_t d;
    asm("cvt.rn.bf16x2.f32 %0, %1, %2;" : "=r"(d) : "f"(hi), "f"(lo));
    return d;
}

// ---------------------------------------------------------------------------
// Fused kernel, 512 threads (16 warps), 1 CTA/SM, grid (128,3) = 384 CTAs.
// MLP: R7 tf32 path, bit-identical F outputs (metric-dominant, untouched).
// Adjacency: bf16 m16n8k16 on an F-bf16x2 smem buffer -> half the k-steps
// (4096 -> 2048 adjacency MMAs/CTA) and half the fragment LDS bytes.
// sB pair layout: pair p -> slot (p&~7) + 2*(p&3) + ((p>>2)&1), so the
// (q, q+4) pair needed by each fragment is one LDS.64.
// smem: sZ [256][STR] f32 + sW [2][64][STR] f32 + bias[128] + sB [256][BSTR] u32
//     = 73728 + 36864 + 512 + 40960 = 152064 B
// ---------------------------------------------------------------------------
__global__ void __launch_bounds__(512, 1) fused_kernel(
    const float* __restrict__ z,
    const float* __restrict__ Wa1, const float* __restrict__ ba1,
    const float* __restrict__ Wa2, const float* __restrict__ ba2,
    const float* __restrict__ Wb1, const float* __restrict__ bb1,
    const float* __restrict__ Wb2, const float* __restrict__ bb2,
    const float* __restrict__ Wt1, const float* __restrict__ bt1,
    const float* __restrict__ Wt2, const float* __restrict__ bt2,
    float* __restrict__ out)
{
    extern __shared__ __align__(16) float smem[];
    float*    sZ    = smem;                    // [256][STR], k-permuted f32
    float*    sW    = smem + 256 * STR;        // [2][64][STR] tf32 weights
    float*    sBias = sW + 2 * 64 * STR;       // [128]
    uint32_t* sB    = (uint32_t*)(sBias + 128); // [256][BSTR] F as bf16x2 pairs

    const int g    = blockIdx.x;
    const int type = blockIdx.y;

    const float *W1, *B1, *W2, *B2;
    if (type == 0)      { W1 = Wa1; B1 = ba1; W2 = Wa2; B2 = ba2; }
    else if (type == 1) { W1 = Wb1; B1 = bb1; W2 = Wb2; B2 = bb2; }
    else                { W1 = Wt1; B1 = bt1; W2 = Wt2; B2 = bt2; }

    const int tid = threadIdx.x;
    const int warp = tid >> 5, lane = tid & 31;
    const int g8 = lane >> 2, q = lane & 3;

    // ---------------- Phase 0: loads ----------------
    const float* zG = z + (size_t)g * NODES * CH;
    for (int i = tid; i < NODES * CH / 4; i += 512) {       // 4096 float4s
        int r = i >> 4, c4 = (i & 15) * 4;
        float4 v = *(const float4*)&zG[r * CH + c4];
        float* row = &sZ[r * STR];
        row[posk(c4 + 0)] = v.x;
        row[posk(c4 + 1)] = v.y;
        row[posk(c4 + 2)] = v.z;
        row[posk(c4 + 3)] = v.w;
    }
#pragma unroll 1
    for (int l = 0; l < 2; ++l) {
        const float* W = l ? W2 : W1;
        float* w = sW + l * 64 * STR;
        for (int i = tid; i < 64 * 64; i += 512) {
            int k = i >> 6, n = i & 63;
            w[n * STR + posk(k)] = tf32r(W[i]);   // coalesced read, scattered store
        }
    }
    if (tid < 64)       sBias[tid] = B1[tid];
    else if (tid < 128) sBias[tid] = B2[tid - 64];
    __syncthreads();

    // ---------------- Phase 1: MLP (warp-private 16 rows, no block syncs) ----
    const int row0 = warp * 16;
    const int kq2 = 2 * q;
    float* __restrict__ fout = out + F_BASE + (size_t)type * F_ELEMS
                                   + (size_t)g * NODES * CH;

#pragma unroll 1
    for (int l = 0; l < 2; ++l) {
        const float* Wt   = sW + l * 64 * STR;
        const float* bias = sBias + l * 64;

        float acc[8][4];
#pragma unroll
        for (int nt = 0; nt < 8; ++nt)
#pragma unroll
            for (int e = 0; e < 4; ++e) acc[nt][e] = 0.0f;

#pragma unroll
        for (int k0 = 0; k0 < 8; ++k0) {
            const int kp = k0 * 8 + kq2;
            float2 la = *(const float2*)&sZ[(row0 + g8)     * STR + kp];
            float2 lb = *(const float2*)&sZ[(row0 + g8 + 8) * STR + kp];
            uint32_t af[4];
            af[0] = __float_as_uint(tf32r(la.x));
            af[1] = __float_as_uint(tf32r(lb.x));
            af[2] = __float_as_uint(tf32r(la.y));
            af[3] = __float_as_uint(tf32r(lb.y));
#pragma unroll
            for (int nt = 0; nt < 8; ++nt) {
                float2 wb = *(const float2*)&Wt[(nt * 8 + g8) * STR + kp];
                uint32_t bf[2] = {__float_as_uint(wb.x), __float_as_uint(wb.y)};
                mma_tf32(acc[nt], af, bf);
            }
        }
        __syncwarp();   // all lanes done reading this warp's sZ rows

#pragma unroll
        for (int nt = 0; nt < 8; ++nt) {
            const int c0 = nt * 8 + 2 * q;
            float v0 = fmaxf(acc[nt][0] + bias[c0],     0.0f);
            float v1 = fmaxf(acc[nt][1] + bias[c0 + 1], 0.0f);
            float v2 = fmaxf(acc[nt][2] + bias[c0],     0.0f);
            float v3 = fmaxf(acc[nt][3] + bias[c0 + 1], 0.0f);
            if (l == 0) {
                const int p0 = posk(c0), p1 = posk(c0 + 1);
                float* rA = &sZ[(row0 + g8) * STR];
                float* rB = &sZ[(row0 + g8 + 8) * STR];
                rA[p0] = v0; rA[p1] = v1;
                rB[p0] = v2; rB[p1] = v3;
            } else {
                // F: fp32 -> gmem (bit-identical to R7); bf16x2 pair -> sB
                *(float2*)&fout[(size_t)(row0 + g8)     * CH + c0] = make_float2(v0, v1);
                *(float2*)&fout[(size_t)(row0 + g8 + 8) * CH + c0] = make_float2(v2, v3);
                // pair index p = nt*4+q -> slot (nt>>1)*8 + 2q + (nt&1)
                const int p2 = (nt >> 1) * 8 + 2 * q + (nt & 1);
                sB[(row0 + g8)     * BSTR + p2] = pack_bf16(v0, v1);
                sB[(row0 + g8 + 8) * BSTR + p2] = pack_bf16(v2, v3);
            }
        }
        __syncwarp();   // stores visible before next layer's lane-crossed reads
    }
    __syncthreads();    // full F (bf16x2) visible to all warps

    // ---------------- Phase 3: adjacency (bf16, K=16 per mma) ----------------
    const int wm2 = warp >> 3;          // 0..1 -> 64-row block within half
    const int wn  = (warp & 7) * 32;    // 0..224
    float* __restrict__ O = out + ((size_t)type * NGRAPH + g) * (NODES * NODES);

#pragma unroll 1
    for (int hm = 0; hm < 2; ++hm) {
        const int rbase = hm * 128 + wm2 * 64;

        float acc[4][4][4];
#pragma unroll
        for (int mt = 0; mt < 4; ++mt)
#pragma unroll
            for (int nt = 0; nt < 4; ++nt)
#pragma unroll
                for (int e = 0; e < 4; ++e) acc[mt][nt][e] = 0.0f;

#pragma unroll
        for (int kc4 = 0; kc4 < 4; ++kc4) {      // 4 chunks of K=16
            const int kp = kc4 * 8 + kq2;        // u32 slot of the (q,q+4) pair
            uint32_t af[4][4], bf[4][2];
#pragma unroll
            for (int mt = 0; mt < 4; ++mt) {
                uint2 la = *(const uint2*)&sB[(rbase + mt * 16 + g8)     * BSTR + kp];
                uint2 lb = *(const uint2*)&sB[(rbase + mt * 16 + g8 + 8) * BSTR + kp];
                af[mt][0] = la.x;   // A[r][2q..2q+1]
                af[mt][1] = lb.x;   // A[r+8][2q..2q+1]
                af[mt][2] = la.y;   // A[r][2q+8..2q+9]
                af[mt][3] = lb.y;   // A[r+8][2q+8..2q+9]
            }
#pragma unroll
            for (int nt = 0; nt < 4; ++nt) {
                uint2 vb = *(const uint2*)&sB[(wn + nt * 8 + g8) * BSTR + kp];
                bf[nt][0] = vb.x;
                bf[nt][1] = vb.y;
            }
#pragma unroll
            for (int mt = 0; mt < 4; ++mt)
#pragma unroll
                for (int nt = 0; nt < 4; ++nt)
                    mma_bf16(acc[mt][nt], af[mt], bf[nt]);
        }

#pragma unroll
        for (int mt = 0; mt < 4; ++mt) {
            const int row = rbase + mt * 16 + g8;
#pragma unroll
            for (int nt = 0; nt < 4; ++nt) {
                const int col = wn + nt * 8 + 2 * q;
                float2 v0, v1;
                v0.x = sigmoid_fast(acc[mt][nt][0]);
                v0.y = sigmoid_fast(acc[mt][nt][1]);
                v1.x = sigmoid_fast(acc[mt][nt][2]);
                v1.y = sigmoid_fast(acc[mt][nt][3]);
                *(float2*)&O[(size_t)row * NODES + col]       = v0;
                *(float2*)&O[(size_t)(row + 8) * NODES + col] = v1;
            }
        }
    }
}

extern "C" void kernel_launch(void* const* d_in, const int* in_sizes, int n_in,
                              void* d_out, int out_size) {
    const float* z   = (const float*)d_in[0];
    // d_in[1] = batch (int64): uniform segments, unused
    const float* Wa1 = (const float*)d_in[2];
    const float* ba1 = (const float*)d_in[3];
    const float* Wa2 = (const float*)d_in[4];
    const float* ba2 = (const float*)d_in[5];
    const float* Wb1 = (const float*)d_in[6];
    const float* bb1 = (const float*)d_in[7];
    const float* Wb2 = (const float*)d_in[8];
    const float* bb2 = (const float*)d_in[9];
    const float* Wt1 = (const float*)d_in[10];
    const float* bt1 = (const float*)d_in[11];
    const float* Wt2 = (const float*)d_in[12];
    const float* bt2 = (const float*)d_in[13];
    float* out = (float*)d_out;

    const int smem_bytes = (256 * STR + 2 * 64 * STR + 128) * (int)sizeof(float)
                         + 256 * BSTR * (int)sizeof(uint32_t);   // 152064
    cudaFuncSetAttribute(fused_kernel, cudaFuncAttributeMaxDynamicSharedMemorySize, smem_bytes);
    fused_kernel<<<dim3(NGRAPH, 3), 512, smem_bytes>>>(
        z, Wa1, ba1, Wa2, ba2, Wb1, bb1, Wb2, bb2, Wt1, bt1, Wt2, bt2, out);
}